// round 14
// baseline (speedup 1.0000x reference)
#include <cuda_runtime.h>
#include <cuda_bf16.h>
#include <cstdint>
#include <cstddef>

// ---------------------------------------------------------------------------
// InputAttention on GB300 — round 14
//   Base = r13 (1857us best). ONE change: gemm_qk fragment loads switched
//   from 16x LDS.32 to 4x ldmatrix per k16 step (qk is L1/issue-bound:
//   L1=70%, issue=34%, DRAM only 40%). Identical bytes, identical fragments.
// ---------------------------------------------------------------------------

#define NROWS 32768
using bf16 = __nv_bfloat16;

__device__ bf16 g_qn[(size_t)NROWS * 1024];
__device__ bf16 g_q [(size_t)NROWS * 1024];
__device__ bf16 g_u [(size_t)NROWS * 16 * 1024];   // u[n][h][d]; w in place
__device__ bf16 g_o [(size_t)NROWS * 1024];
__device__ bf16 g_wq[1024 * 1024];
__device__ bf16 g_wk[1024 * 1024];
__device__ bf16 g_wv[1024 * 1024];
__device__ bf16 g_wo[1024 * 1024];

// ---------------- PTX helpers ----------------
__device__ __forceinline__ uint32_t smem_u32(const void* p) {
    return (uint32_t)__cvta_generic_to_shared(p);
}
__device__ __forceinline__ void cp16(void* s, const void* g) {
    asm volatile("cp.async.cg.shared.global [%0], [%1], 16;"
                 :: "r"(smem_u32(s)), "l"(g));
}
__device__ __forceinline__ void cp_commit() { asm volatile("cp.async.commit_group;"); }
template<int N> __device__ __forceinline__ void cp_wait() {
    asm volatile("cp.async.wait_group %0;" :: "n"(N));
}
__device__ __forceinline__ void ldsm4(uint32_t* r, const void* p) {
    asm volatile("ldmatrix.sync.aligned.m8n8.x4.shared.b16 {%0,%1,%2,%3},[%4];"
        : "=r"(r[0]), "=r"(r[1]), "=r"(r[2]), "=r"(r[3]) : "r"(smem_u32(p)));
}
__device__ __forceinline__ void ldsm4t(uint32_t* r, const void* p) {
    asm volatile("ldmatrix.sync.aligned.m8n8.x4.trans.shared.b16 {%0,%1,%2,%3},[%4];"
        : "=r"(r[0]), "=r"(r[1]), "=r"(r[2]), "=r"(r[3]) : "r"(smem_u32(p)));
}
__device__ __forceinline__ void mma16816(float* c, const uint32_t* a, const uint32_t* b) {
    asm volatile(
        "mma.sync.aligned.m16n8k16.row.col.f32.bf16.bf16.f32 "
        "{%0,%1,%2,%3},{%4,%5,%6,%7},{%8,%9},{%0,%1,%2,%3};"
        : "+f"(c[0]), "+f"(c[1]), "+f"(c[2]), "+f"(c[3])
        : "r"(a[0]), "r"(a[1]), "r"(a[2]), "r"(a[3]), "r"(b[0]), "r"(b[1]));
}
__device__ __forceinline__ uint32_t packbf2(float x, float y) {
    __nv_bfloat162 h = __float22bfloat162_rn(make_float2(x, y));
    return *reinterpret_cast<uint32_t*>(&h);
}

// ---------------- weight convert (fp32 -> bf16) ----------------
__global__ void __launch_bounds__(256) cvt_kernel(
    const float* __restrict__ wq, const float* __restrict__ wk,
    const float* __restrict__ wv, const float* __restrict__ wo)
{
    int i = blockIdx.x * 256 + threadIdx.x;
    float4 a = ((const float4*)wq)[i];
    ((uint2*)g_wq)[i] = make_uint2(packbf2(a.x, a.y), packbf2(a.z, a.w));
    a = ((const float4*)wk)[i];
    ((uint2*)g_wk)[i] = make_uint2(packbf2(a.x, a.y), packbf2(a.z, a.w));
    a = ((const float4*)wv)[i];
    ((uint2*)g_wv)[i] = make_uint2(packbf2(a.x, a.y), packbf2(a.z, a.w));
    a = ((const float4*)wo)[i];
    ((uint2*)g_wo)[i] = make_uint2(packbf2(a.x, a.y), packbf2(a.z, a.w));
}

// ---------------- block reduce (for ln_q) ----------------
__device__ __forceinline__ float block_reduce_sum(float v, float* sh) {
#pragma unroll
    for (int o = 16; o > 0; o >>= 1) v += __shfl_xor_sync(0xffffffffu, v, o);
    int lane = threadIdx.x & 31, w = threadIdx.x >> 5;
    if (lane == 0) sh[w] = v;
    __syncthreads();
    if (threadIdx.x < 8) {
        float t = sh[threadIdx.x];
#pragma unroll
        for (int o = 4; o > 0; o >>= 1) t += __shfl_xor_sync(0xffu, t, o);
        if (threadIdx.x == 0) sh[0] = t;
    }
    __syncthreads();
    float r = sh[0];
    __syncthreads();
    return r;
}

// ---------------- LN_q: qn = LN(feat) (bf16), block-per-row ----------------
__global__ void __launch_bounds__(256) ln_q_kernel(
    const float* __restrict__ feat,
    const float* __restrict__ gq, const float* __restrict__ bq)
{
    __shared__ float sh[8];
    int n = blockIdx.x, tid = threadIdx.x;
    float4 x = ((const float4*)(feat + (size_t)n * 1024))[tid];
    float s = block_reduce_sum(x.x + x.y + x.z + x.w, sh);
    float mean = s * (1.0f / 1024.0f);
    float dx = x.x - mean, dy = x.y - mean, dz = x.z - mean, dw = x.w - mean;
    float sq = block_reduce_sum(dx * dx + dy * dy + dz * dz + dw * dw, sh);
    float rs = rsqrtf(sq * (1.0f / 1024.0f) + 1e-5f);
    float4 g = ((const float4*)gq)[tid];
    float4 b = ((const float4*)bq)[tid];
    *reinterpret_cast<uint2*>(g_qn + (size_t)n * 1024 + tid * 4) = make_uint2(
        packbf2(dx * rs * g.x + b.x, dy * rs * g.y + b.y),
        packbf2(dz * rs * g.z + b.z, dw * rs * g.w + b.w));
}

// ---------------------------------------------------------------------------
// Standard bf16 GEMM (r10/r13): BK=64, 2-stage cp.async, dynamic smem.
// ---------------------------------------------------------------------------
template<int BN, bool EPI, bool CF32>
__global__ void __launch_bounds__(256) gemm_bf16(
    const bf16* __restrict__ A, long aBS, int lda,
    const bf16* __restrict__ B, long bBS, int ldb,
    void* __restrict__ Cv, long cBS, int ldc,
    int K, const float* __restrict__ bias, const float* __restrict__ resid)
{
    constexpr int BM = 128, BK = 64;
    constexpr int AP = BK + 8;
    constexpr int BP = BN + 8;
    constexpr int NF = BN / 16;
    extern __shared__ __align__(16) bf16 dsm[];
    bf16* As = dsm;
    bf16* Bs = dsm + 2 * BM * AP;

    int z = blockIdx.z;
    A += (size_t)z * aBS;
    B += (size_t)z * bBS;

    int bm = blockIdx.y * BM, bn = blockIdx.x * BN;
    int tid = threadIdx.x, lane = tid & 31, wid = tid >> 5;
    int wm = (wid >> 1) * 32, wn = (wid & 1) * (BN / 2);

    float acc[2][NF][4];
#pragma unroll
    for (int i = 0; i < 2; i++)
#pragma unroll
        for (int j = 0; j < NF; j++)
#pragma unroll
            for (int k = 0; k < 4; k++) acc[i][j][k] = 0.f;

    auto loadA = [&](int buf, int k0) {
        bf16* dst = As + buf * BM * AP;
#pragma unroll
        for (int it = 0; it < 4; it++) {
            int i = tid + it * 256;
            int r = i >> 3, kc = i & 7;
            cp16(dst + r * AP + kc * 8,
                 A + (size_t)(bm + r) * lda + k0 + kc * 8);
        }
    };
    auto loadB = [&](int buf, int k0) {
        bf16* dst = Bs + buf * BK * BP;
        constexpr int CH = BK * BN / 8;
#pragma unroll
        for (int it = 0; it < CH / 256; it++) {
            int i = tid + it * 256;
            int r = i / (BN / 8), nc = i % (BN / 8);
            cp16(dst + r * BP + nc * 8,
                 B + (size_t)(k0 + r) * ldb + bn + nc * 8);
        }
    };
    auto compute = [&](int buf) {
        const bf16* a_s = As + buf * BM * AP;
        const bf16* b_s = Bs + buf * BK * BP;
#pragma unroll
        for (int kk = 0; kk < BK; kk += 16) {
            uint32_t af[2][4];
#pragma unroll
            for (int mf = 0; mf < 2; mf++) {
                int r = wm + mf * 16 + ((lane >> 3) & 1) * 8 + (lane & 7);
                int c = kk + (lane >> 4) * 8;
                ldsm4(af[mf], a_s + r * AP + c);
            }
            uint32_t bfr[NF][2];
#pragma unroll
            for (int n2 = 0; n2 < NF / 2; n2++) {
                int kr = kk + ((lane >> 3) & 1) * 8 + (lane & 7);
                int nc = wn + n2 * 16 + (lane >> 4) * 8;
                uint32_t t[4];
                ldsm4t(t, b_s + kr * BP + nc);
                bfr[2 * n2][0] = t[0];     bfr[2 * n2][1] = t[1];
                bfr[2 * n2 + 1][0] = t[2]; bfr[2 * n2 + 1][1] = t[3];
            }
#pragma unroll
            for (int mf = 0; mf < 2; mf++)
#pragma unroll
                for (int nf = 0; nf < NF; nf++)
                    mma16816(acc[mf][nf], af[mf], bfr[nf]);
        }
    };

    loadA(0, 0); loadB(0, 0); cp_commit();
    int nIter = K / BK;
    for (int it = 0; it < nIter; it++) {
        if (it + 1 < nIter) {
            loadA((it + 1) & 1, (it + 1) * BK);
            loadB((it + 1) & 1, (it + 1) * BK);
            cp_commit();
            cp_wait<1>();
        } else {
            cp_wait<0>();
        }
        __syncthreads();
        compute(it & 1);
        __syncthreads();
    }

#pragma unroll
    for (int mf = 0; mf < 2; mf++) {
#pragma unroll
        for (int nf = 0; nf < NF; nf++) {
            int r = bm + wm + mf * 16 + (lane >> 2);
            int c = bn + wn + nf * 8 + (lane & 3) * 2;
            float v0 = acc[mf][nf][0], v1 = acc[mf][nf][1];
            float v2 = acc[mf][nf][2], v3 = acc[mf][nf][3];
            if constexpr (CF32) {
                float* C = (float*)Cv + (size_t)z * cBS;
                if constexpr (EPI) {
                    v0 += bias[c]     + resid[(size_t)r * ldc + c];
                    v1 += bias[c + 1] + resid[(size_t)r * ldc + c + 1];
                    v2 += bias[c]     + resid[(size_t)(r + 8) * ldc + c];
                    v3 += bias[c + 1] + resid[(size_t)(r + 8) * ldc + c + 1];
                }
                *(float2*)&C[(size_t)r * ldc + c]       = make_float2(v0, v1);
                *(float2*)&C[(size_t)(r + 8) * ldc + c] = make_float2(v2, v3);
            } else {
                bf16* C = (bf16*)Cv + (size_t)z * cBS;
                *(uint32_t*)&C[(size_t)r * ldc + c]       = packbf2(v0, v1);
                *(uint32_t*)&C[(size_t)(r + 8) * ldc + c] = packbf2(v2, v3);
            }
        }
    }
}

// ---------------------------------------------------------------------------
// gemm_qk (round 14): one-shot [64n x 64d] blocks, 128 threads.
//   Fragment loads via ldmatrix (4 per k16 step, was 16 LDS.32).
//   A rows are m (m-major, ldsm4 non-trans); B rows are n (n-major — ALSO
//   ldsm4 non-trans: lane gets (row=lane>>2, kpair=lane&3), exactly the
//   mma.16816 B-operand mapping).
// ---------------------------------------------------------------------------
__global__ void __launch_bounds__(128) gemm_qk_kernel()
{
    constexpr int P = 72;
    __shared__ __align__(16) bf16 As[64 * P];
    __shared__ __align__(16) bf16 Bs[64 * P];

    int z = blockIdx.z;
    int bn = blockIdx.x * 64;
    int bm = blockIdx.y * 64;
    int tid = threadIdx.x, lane = tid & 31, wid = tid >> 5;
    int wm = (wid >> 1) * 32, wn = (wid & 1) * 32;

#pragma unroll
    for (int it = 0; it < 4; it++) {
        int i = tid + it * 128;
        int r = i >> 3, kc = i & 7;
        cp16(&As[r * P + kc * 8], g_q + (size_t)(bm + r) * 1024 + z * 64 + kc * 8);
        cp16(&Bs[r * P + kc * 8], g_wk + (size_t)(bn + r) * 1024 + z * 64 + kc * 8);
    }
    cp_commit(); cp_wait<0>();
    __syncthreads();

    float acc[2][4][4];
#pragma unroll
    for (int i = 0; i < 2; i++)
#pragma unroll
        for (int j = 0; j < 4; j++)
#pragma unroll
            for (int k = 0; k < 4; k++) acc[i][j][k] = 0.f;

#pragma unroll
    for (int kk = 0; kk < 64; kk += 16) {
        // ldmatrix row/col per lane (shared by A and B addressing)
        int fr = ((lane >> 3) & 1) * 8 + (lane & 7);   // row within 16-row group
        int fc = kk + (lane >> 4) * 8;                 // k lo/hi half

        uint32_t af[2][4];
#pragma unroll
        for (int mf = 0; mf < 2; mf++)
            ldsm4(af[mf], &As[(wm + mf * 16 + fr) * P + fc]);

        uint32_t bfr[4][2];
#pragma unroll
        for (int n2 = 0; n2 < 2; n2++) {
            uint32_t t[4];
            ldsm4(t, &Bs[(wn + n2 * 16 + fr) * P + fc]);
            // t0=(n0-7,klo) t1=(n8-15,klo) t2=(n0-7,khi) t3=(n8-15,khi)
            bfr[2 * n2][0] = t[0];     bfr[2 * n2][1] = t[2];
            bfr[2 * n2 + 1][0] = t[1]; bfr[2 * n2 + 1][1] = t[3];
        }
#pragma unroll
        for (int mf = 0; mf < 2; mf++)
#pragma unroll
            for (int nf = 0; nf < 4; nf++)
                mma16816(acc[mf][nf], af[mf], bfr[nf]);
    }
    __syncthreads();

#pragma unroll
    for (int mf = 0; mf < 2; mf++) {
#pragma unroll
        for (int nf = 0; nf < 4; nf++) {
            int r = wm + mf * 16 + (lane >> 2);
            int c = wn + nf * 8 + (lane & 3) * 2;
            *(uint32_t*)&As[r * P + c]       = packbf2(acc[mf][nf][0], acc[mf][nf][1]);
            *(uint32_t*)&As[(r + 8) * P + c] = packbf2(acc[mf][nf][2], acc[mf][nf][3]);
        }
    }
    __syncthreads();

    bf16* C = g_u + (size_t)bm * 16384 + (size_t)z * 1024 + bn;
#pragma unroll
    for (int it = 0; it < 4; it++) {
        int i = tid + it * 128;
        int r = i >> 3, kc = i & 7;
        *(float4*)(C + (size_t)r * 16384 + kc * 8) = *(const float4*)&As[r * P + kc * 8];
    }
}

// ---------------------------------------------------------------------------
// attn_fused (r13, measured): 288 threads (9 warps).
// ---------------------------------------------------------------------------
__global__ void __launch_bounds__(288) attn_fused_kernel(
    const float* __restrict__ feat, const float* __restrict__ ctx,
    const float* __restrict__ gc, const float* __restrict__ bc)
{
    __shared__ __align__(16) bf16 cn_s[9 * 1024];   // 18 KB
    __shared__ float att[144];
    int n = blockIdx.x, tid = threadIdx.x, lane = tid & 31, wid = tid >> 5;

    // ---- Phase A: warp-parallel LN_c (warp l handles row l) ----
    {
        int l = wid;
        const float* src = (l == 0) ? feat + (size_t)n * 1024
                                    : ctx + ((size_t)n * 8 + (l - 1)) * 1024;
        float4 x[8];
        float s = 0.f;
#pragma unroll
        for (int j = 0; j < 8; j++) {
            x[j] = ((const float4*)src)[lane + j * 32];
            s += (x[j].x + x[j].y) + (x[j].z + x[j].w);
        }
#pragma unroll
        for (int o = 16; o > 0; o >>= 1) s += __shfl_xor_sync(0xffffffffu, s, o);
        float mean = s * (1.0f / 1024.0f);
        float sq = 0.f;
#pragma unroll
        for (int j = 0; j < 8; j++) {
            x[j].x -= mean; x[j].y -= mean; x[j].z -= mean; x[j].w -= mean;
            sq += x[j].x * x[j].x + x[j].y * x[j].y
                + x[j].z * x[j].z + x[j].w * x[j].w;
        }
#pragma unroll
        for (int o = 16; o > 0; o >>= 1) sq += __shfl_xor_sync(0xffffffffu, sq, o);
        float rs = rsqrtf(sq * (1.0f / 1024.0f) + 1e-5f);
#pragma unroll
        for (int j = 0; j < 8; j++) {
            int idx = lane + j * 32;
            float4 g = ((const float4*)gc)[idx];
            float4 b = ((const float4*)bc)[idx];
            *(uint2*)(cn_s + l * 1024 + idx * 4) = make_uint2(
                packbf2(x[j].x * rs * g.x + b.x, x[j].y * rs * g.y + b.y),
                packbf2(x[j].z * rs * g.z + b.z, x[j].w * rs * g.w + b.w));
        }
    }
    __syncthreads();

    // ---- Phase B: scores (warps 0..7, heads {w, w+8}, u in registers) ----
    if (wid < 8) {
        uint4 u0[4], u1[4];
        const uint4* ga = (const uint4*)(g_u + (size_t)n * 16384 + (size_t)wid * 1024);
        const uint4* gb = (const uint4*)(g_u + (size_t)n * 16384 + (size_t)(wid + 8) * 1024);
#pragma unroll
        for (int j = 0; j < 4; j++) { u0[j] = ga[lane + j * 32]; u1[j] = gb[lane + j * 32]; }

#pragma unroll
        for (int l = 0; l < 9; l++) {
            const uint4* cc = (const uint4*)(cn_s + l * 1024);
            float s0 = 0.f, s1 = 0.f;
#pragma unroll
            for (int j = 0; j < 4; j++) {
                uint4 cb = cc[lane + j * 32];
                const uint32_t* cw = &cb.x;
                const uint32_t* aw = &u0[j].x;
                const uint32_t* bw = &u1[j].x;
#pragma unroll
                for (int q = 0; q < 4; q++) {
                    float2 cv = __bfloat1622float2(*(__nv_bfloat162*)&cw[q]);
                    float2 av = __bfloat1622float2(*(__nv_bfloat162*)&aw[q]);
                    float2 bv = __bfloat1622float2(*(__nv_bfloat162*)&bw[q]);
                    s0 = fmaf(av.x, cv.x, fmaf(av.y, cv.y, s0));
                    s1 = fmaf(bv.x, cv.x, fmaf(bv.y, cv.y, s1));
                }
            }
#pragma unroll
            for (int o = 16; o > 0; o >>= 1) {
                s0 += __shfl_xor_sync(0xffffffffu, s0, o);
                s1 += __shfl_xor_sync(0xffffffffu, s1, o);
            }
            if (lane == 0) {
                att[wid * 9 + l]       = s0;
                att[(wid + 8) * 9 + l] = s1;
            }
        }
    }
    __syncthreads();

    // ---- softmax over l (scale 0.125) ----
    if (tid < 16) {
        float m = -1e30f;
#pragma unroll
        for (int l = 0; l < 9; l++) m = fmaxf(m, att[tid * 9 + l]);
        float e[9], sum = 0.f;
#pragma unroll
        for (int l = 0; l < 9; l++) {
            e[l] = __expf((att[tid * 9 + l] - m) * 0.125f);
            sum += e[l];
        }
        float inv = 1.0f / sum;
#pragma unroll
        for (int l = 0; l < 9; l++) att[tid * 9 + l] = e[l] * inv;
    }
    __syncthreads();

    // ---- w-phase: one pass, 4 bf16 per thread (uint2 LDS + uint2 STG) ----
    if (tid < 256) {
        bf16* ug = g_u + (size_t)n * 16384;
        int dp4 = tid;
        float2 c[9][2];
#pragma unroll
        for (int l = 0; l < 9; l++) {
            uint2 v = ((const uint2*)cn_s)[l * 256 + dp4];
            c[l][0] = __bfloat1622float2(*(__nv_bfloat162*)&v.x);
            c[l][1] = __bfloat1622float2(*(__nv_bfloat162*)&v.y);
        }
#pragma unroll
        for (int h = 0; h < 16; h++) {
            float s0 = 0.f, s1 = 0.f, s2 = 0.f, s3 = 0.f;
#pragma unroll
            for (int l = 0; l < 9; l++) {
                float a = att[h * 9 + l];
                s0 = fmaf(a, c[l][0].x, s0);
                s1 = fmaf(a, c[l][0].y, s1);
                s2 = fmaf(a, c[l][1].x, s2);
                s3 = fmaf(a, c[l][1].y, s3);
            }
            *(uint2*)(ug + h * 1024 + dp4 * 4)
                = make_uint2(packbf2(s0, s1), packbf2(s2, s3));
        }
    }
}

// ---------------------------------------------------------------------------
extern "C" void kernel_launch(void* const* d_in, const int* in_sizes, int n_in,
                              void* d_out, int out_size)
{
    const float* feat    = (const float*)d_in[0];
    const float* context = (const float*)d_in[1];
    const float* ln_q_g  = (const float*)d_in[2];
    const float* ln_q_b  = (const float*)d_in[3];
    const float* ln_c_g  = (const float*)d_in[4];
    const float* ln_c_b  = (const float*)d_in[5];
    const float* Wq      = (const float*)d_in[6];
    const float* Wk      = (const float*)d_in[7];
    const float* Wv      = (const float*)d_in[8];
    const float* Wout    = (const float*)d_in[9];
    const float* bout    = (const float*)d_in[10];
    float* out = (float*)d_out;
    (void)in_sizes; (void)n_in; (void)out_size;

    bf16 *p_qn, *p_q, *p_u, *p_o, *p_wq, *p_wv, *p_wo;
    cudaGetSymbolAddress((void**)&p_qn, g_qn);
    cudaGetSymbolAddress((void**)&p_q,  g_q);
    cudaGetSymbolAddress((void**)&p_u,  g_u);
    cudaGetSymbolAddress((void**)&p_o,  g_o);
    cudaGetSymbolAddress((void**)&p_wq, g_wq);
    cudaGetSymbolAddress((void**)&p_wv, g_wv);
    cudaGetSymbolAddress((void**)&p_wo, g_wo);

    const int SMEM_BN128 = (2 * 128 * 72 + 2 * 64 * 136) * 2;   // 71680 B
    const int SMEM_BN64  = (2 * 128 * 72 + 2 * 64 * 72) * 2;    // 55296 B
    cudaFuncSetAttribute(gemm_bf16<128, false, false>,
                         cudaFuncAttributeMaxDynamicSharedMemorySize, SMEM_BN128);
    cudaFuncSetAttribute(gemm_bf16<128, true, true>,
                         cudaFuncAttributeMaxDynamicSharedMemorySize, SMEM_BN128);
    cudaFuncSetAttribute(gemm_bf16<64, false, false>,
                         cudaFuncAttributeMaxDynamicSharedMemorySize, SMEM_BN64);

    // 0) weights fp32 -> bf16
    cvt_kernel<<<1024, 256>>>(Wq, Wk, Wv, Wout);

    // 1) qn = LN_q(feat)
    ln_q_kernel<<<NROWS, 256>>>(feat, ln_q_g, ln_q_b);

    // 2) q = qn @ Wq
    gemm_bf16<128, false, false><<<dim3(8, 256, 1), 256, SMEM_BN128>>>(
        p_qn, 0, 1024, p_wq, 0, 1024, p_q, 0, 1024, 1024, nullptr, nullptr);

    // 3) u[n][z] = q_z @ Wk_z^T  (K=64, one-shot 64x64 blocks, ldmatrix)
    gemm_qk_kernel<<<dim3(16, 512, 16), 128>>>();

    // 4) fused warp-parallel LN_c + scores + softmax + w (in place over u)
    attn_fused_kernel<<<NROWS, 288>>>(feat, context, ln_c_g, ln_c_b);

    // 5) o_z = w_z @ Wv_z
    gemm_bf16<64, false, false><<<dim3(1, 256, 16), 256, SMEM_BN64>>>(
        p_u, 1024, 16384, p_wv, 64, 1024, p_o, 64, 1024, 1024, nullptr, nullptr);

    // 6) out = o @ Wout + bout + feat  (fp32)
    gemm_bf16<128, true, true><<<dim3(8, 256, 1), 256, SMEM_BN128>>>(
        p_o, 0, 1024, p_wo, 0, 1024, out, 0, 1024, 1024, bout, feat);
}

// round 15
// speedup vs baseline: 1.0086x; 1.0086x over previous
#include <cuda_runtime.h>
#include <cuda_bf16.h>
#include <cstdint>
#include <cstddef>

// ---------------------------------------------------------------------------
// InputAttention on GB300 — round 15
//   Base = r13 (1857us best). ONE change: gemm_qk reverted to the r5
//   geometry ([64n x 128d] one-shot blocks, 128 threads) which measured
//   326us vs 343-347us for the 64x64 shape (6 measurements). Scalar LDS
//   fragments kept (ldmatrix measured neutral in r14).
// ---------------------------------------------------------------------------

#define NROWS 32768
using bf16 = __nv_bfloat16;

__device__ bf16 g_qn[(size_t)NROWS * 1024];
__device__ bf16 g_q [(size_t)NROWS * 1024];
__device__ bf16 g_u [(size_t)NROWS * 16 * 1024];   // u[n][h][d]; w in place
__device__ bf16 g_o [(size_t)NROWS * 1024];
__device__ bf16 g_wq[1024 * 1024];
__device__ bf16 g_wk[1024 * 1024];
__device__ bf16 g_wv[1024 * 1024];
__device__ bf16 g_wo[1024 * 1024];

// ---------------- PTX helpers ----------------
__device__ __forceinline__ uint32_t smem_u32(const void* p) {
    return (uint32_t)__cvta_generic_to_shared(p);
}
__device__ __forceinline__ void cp16(void* s, const void* g) {
    asm volatile("cp.async.cg.shared.global [%0], [%1], 16;"
                 :: "r"(smem_u32(s)), "l"(g));
}
__device__ __forceinline__ void cp_commit() { asm volatile("cp.async.commit_group;"); }
template<int N> __device__ __forceinline__ void cp_wait() {
    asm volatile("cp.async.wait_group %0;" :: "n"(N));
}
__device__ __forceinline__ void ldsm4(uint32_t* r, const void* p) {
    asm volatile("ldmatrix.sync.aligned.m8n8.x4.shared.b16 {%0,%1,%2,%3},[%4];"
        : "=r"(r[0]), "=r"(r[1]), "=r"(r[2]), "=r"(r[3]) : "r"(smem_u32(p)));
}
__device__ __forceinline__ void ldsm4t(uint32_t* r, const void* p) {
    asm volatile("ldmatrix.sync.aligned.m8n8.x4.trans.shared.b16 {%0,%1,%2,%3},[%4];"
        : "=r"(r[0]), "=r"(r[1]), "=r"(r[2]), "=r"(r[3]) : "r"(smem_u32(p)));
}
__device__ __forceinline__ void mma16816(float* c, const uint32_t* a, const uint32_t* b) {
    asm volatile(
        "mma.sync.aligned.m16n8k16.row.col.f32.bf16.bf16.f32 "
        "{%0,%1,%2,%3},{%4,%5,%6,%7},{%8,%9},{%0,%1,%2,%3};"
        : "+f"(c[0]), "+f"(c[1]), "+f"(c[2]), "+f"(c[3])
        : "r"(a[0]), "r"(a[1]), "r"(a[2]), "r"(a[3]), "r"(b[0]), "r"(b[1]));
}
__device__ __forceinline__ uint32_t packbf2(float x, float y) {
    __nv_bfloat162 h = __float22bfloat162_rn(make_float2(x, y));
    return *reinterpret_cast<uint32_t*>(&h);
}

// ---------------- weight convert (fp32 -> bf16) ----------------
__global__ void __launch_bounds__(256) cvt_kernel(
    const float* __restrict__ wq, const float* __restrict__ wk,
    const float* __restrict__ wv, const float* __restrict__ wo)
{
    int i = blockIdx.x * 256 + threadIdx.x;
    float4 a = ((const float4*)wq)[i];
    ((uint2*)g_wq)[i] = make_uint2(packbf2(a.x, a.y), packbf2(a.z, a.w));
    a = ((const float4*)wk)[i];
    ((uint2*)g_wk)[i] = make_uint2(packbf2(a.x, a.y), packbf2(a.z, a.w));
    a = ((const float4*)wv)[i];
    ((uint2*)g_wv)[i] = make_uint2(packbf2(a.x, a.y), packbf2(a.z, a.w));
    a = ((const float4*)wo)[i];
    ((uint2*)g_wo)[i] = make_uint2(packbf2(a.x, a.y), packbf2(a.z, a.w));
}

// ---------------- block reduce (for ln_q) ----------------
__device__ __forceinline__ float block_reduce_sum(float v, float* sh) {
#pragma unroll
    for (int o = 16; o > 0; o >>= 1) v += __shfl_xor_sync(0xffffffffu, v, o);
    int lane = threadIdx.x & 31, w = threadIdx.x >> 5;
    if (lane == 0) sh[w] = v;
    __syncthreads();
    if (threadIdx.x < 8) {
        float t = sh[threadIdx.x];
#pragma unroll
        for (int o = 4; o > 0; o >>= 1) t += __shfl_xor_sync(0xffu, t, o);
        if (threadIdx.x == 0) sh[0] = t;
    }
    __syncthreads();
    float r = sh[0];
    __syncthreads();
    return r;
}

// ---------------- LN_q: qn = LN(feat) (bf16), block-per-row ----------------
__global__ void __launch_bounds__(256) ln_q_kernel(
    const float* __restrict__ feat,
    const float* __restrict__ gq, const float* __restrict__ bq)
{
    __shared__ float sh[8];
    int n = blockIdx.x, tid = threadIdx.x;
    float4 x = ((const float4*)(feat + (size_t)n * 1024))[tid];
    float s = block_reduce_sum(x.x + x.y + x.z + x.w, sh);
    float mean = s * (1.0f / 1024.0f);
    float dx = x.x - mean, dy = x.y - mean, dz = x.z - mean, dw = x.w - mean;
    float sq = block_reduce_sum(dx * dx + dy * dy + dz * dz + dw * dw, sh);
    float rs = rsqrtf(sq * (1.0f / 1024.0f) + 1e-5f);
    float4 g = ((const float4*)gq)[tid];
    float4 b = ((const float4*)bq)[tid];
    *reinterpret_cast<uint2*>(g_qn + (size_t)n * 1024 + tid * 4) = make_uint2(
        packbf2(dx * rs * g.x + b.x, dy * rs * g.y + b.y),
        packbf2(dz * rs * g.z + b.z, dw * rs * g.w + b.w));
}

// ---------------------------------------------------------------------------
// Standard bf16 GEMM (r10/r13): BK=64, 2-stage cp.async, dynamic smem.
// ---------------------------------------------------------------------------
template<int BN, bool EPI, bool CF32>
__global__ void __launch_bounds__(256) gemm_bf16(
    const bf16* __restrict__ A, long aBS, int lda,
    const bf16* __restrict__ B, long bBS, int ldb,
    void* __restrict__ Cv, long cBS, int ldc,
    int K, const float* __restrict__ bias, const float* __restrict__ resid)
{
    constexpr int BM = 128, BK = 64;
    constexpr int AP = BK + 8;
    constexpr int BP = BN + 8;
    constexpr int NF = BN / 16;
    extern __shared__ __align__(16) bf16 dsm[];
    bf16* As = dsm;
    bf16* Bs = dsm + 2 * BM * AP;

    int z = blockIdx.z;
    A += (size_t)z * aBS;
    B += (size_t)z * bBS;

    int bm = blockIdx.y * BM, bn = blockIdx.x * BN;
    int tid = threadIdx.x, lane = tid & 31, wid = tid >> 5;
    int wm = (wid >> 1) * 32, wn = (wid & 1) * (BN / 2);

    float acc[2][NF][4];
#pragma unroll
    for (int i = 0; i < 2; i++)
#pragma unroll
        for (int j = 0; j < NF; j++)
#pragma unroll
            for (int k = 0; k < 4; k++) acc[i][j][k] = 0.f;

    auto loadA = [&](int buf, int k0) {
        bf16* dst = As + buf * BM * AP;
#pragma unroll
        for (int it = 0; it < 4; it++) {
            int i = tid + it * 256;
            int r = i >> 3, kc = i & 7;
            cp16(dst + r * AP + kc * 8,
                 A + (size_t)(bm + r) * lda + k0 + kc * 8);
        }
    };
    auto loadB = [&](int buf, int k0) {
        bf16* dst = Bs + buf * BK * BP;
        constexpr int CH = BK * BN / 8;
#pragma unroll
        for (int it = 0; it < CH / 256; it++) {
            int i = tid + it * 256;
            int r = i / (BN / 8), nc = i % (BN / 8);
            cp16(dst + r * BP + nc * 8,
                 B + (size_t)(k0 + r) * ldb + bn + nc * 8);
        }
    };
    auto compute = [&](int buf) {
        const bf16* a_s = As + buf * BM * AP;
        const bf16* b_s = Bs + buf * BK * BP;
#pragma unroll
        for (int kk = 0; kk < BK; kk += 16) {
            uint32_t af[2][4];
#pragma unroll
            for (int mf = 0; mf < 2; mf++) {
                int r = wm + mf * 16 + ((lane >> 3) & 1) * 8 + (lane & 7);
                int c = kk + (lane >> 4) * 8;
                ldsm4(af[mf], a_s + r * AP + c);
            }
            uint32_t bfr[NF][2];
#pragma unroll
            for (int n2 = 0; n2 < NF / 2; n2++) {
                int kr = kk + ((lane >> 3) & 1) * 8 + (lane & 7);
                int nc = wn + n2 * 16 + (lane >> 4) * 8;
                uint32_t t[4];
                ldsm4t(t, b_s + kr * BP + nc);
                bfr[2 * n2][0] = t[0];     bfr[2 * n2][1] = t[1];
                bfr[2 * n2 + 1][0] = t[2]; bfr[2 * n2 + 1][1] = t[3];
            }
#pragma unroll
            for (int mf = 0; mf < 2; mf++)
#pragma unroll
                for (int nf = 0; nf < NF; nf++)
                    mma16816(acc[mf][nf], af[mf], bfr[nf]);
        }
    };

    loadA(0, 0); loadB(0, 0); cp_commit();
    int nIter = K / BK;
    for (int it = 0; it < nIter; it++) {
        if (it + 1 < nIter) {
            loadA((it + 1) & 1, (it + 1) * BK);
            loadB((it + 1) & 1, (it + 1) * BK);
            cp_commit();
            cp_wait<1>();
        } else {
            cp_wait<0>();
        }
        __syncthreads();
        compute(it & 1);
        __syncthreads();
    }

#pragma unroll
    for (int mf = 0; mf < 2; mf++) {
#pragma unroll
        for (int nf = 0; nf < NF; nf++) {
            int r = bm + wm + mf * 16 + (lane >> 2);
            int c = bn + wn + nf * 8 + (lane & 3) * 2;
            float v0 = acc[mf][nf][0], v1 = acc[mf][nf][1];
            float v2 = acc[mf][nf][2], v3 = acc[mf][nf][3];
            if constexpr (CF32) {
                float* C = (float*)Cv + (size_t)z * cBS;
                if constexpr (EPI) {
                    v0 += bias[c]     + resid[(size_t)r * ldc + c];
                    v1 += bias[c + 1] + resid[(size_t)r * ldc + c + 1];
                    v2 += bias[c]     + resid[(size_t)(r + 8) * ldc + c];
                    v3 += bias[c + 1] + resid[(size_t)(r + 8) * ldc + c + 1];
                }
                *(float2*)&C[(size_t)r * ldc + c]       = make_float2(v0, v1);
                *(float2*)&C[(size_t)(r + 8) * ldc + c] = make_float2(v2, v3);
            } else {
                bf16* C = (bf16*)Cv + (size_t)z * cBS;
                *(uint32_t*)&C[(size_t)r * ldc + c]       = packbf2(v0, v1);
                *(uint32_t*)&C[(size_t)(r + 8) * ldc + c] = packbf2(v2, v3);
            }
        }
    }
}

// ---------------------------------------------------------------------------
// gemm_qk (r5 geometry, measured 326us): one-shot [64n x 128d] blocks,
// 128 threads (4 warps, 2x2, warp tile 32x64), K=64 resident, smem-staged
// coalesced stores into interleaved u[n][h][d].
// ---------------------------------------------------------------------------
__global__ void __launch_bounds__(128) gemm_qk_kernel()
{
    constexpr int P = 72;      // K pad
    constexpr int CP = 136;    // staging pad
    __shared__ __align__(16) char smem_raw[(64 * P + 128 * P) * 2];  // 27648 B
    bf16* As = (bf16*)smem_raw;                       // [64][72]
    bf16* Bs = (bf16*)(smem_raw + 64 * P * 2);        // [128][72]
    bf16* Cs = (bf16*)smem_raw;                       // [64][136] (reuse)

    int z = blockIdx.z;
    int bm = blockIdx.y * 64, bn = blockIdx.x * 128;
    int tid = threadIdx.x, lane = tid & 31, wid = tid >> 5;
    int wm = (wid >> 1) * 32, wn = (wid & 1) * 64;

#pragma unroll
    for (int it = 0; it < 4; it++) {          // A: 512 16B chunks
        int i = tid + it * 128;
        int r = i >> 3, kc = i & 7;
        cp16(&As[r * P + kc * 8], g_q + (size_t)(bm + r) * 1024 + z * 64 + kc * 8);
    }
#pragma unroll
    for (int it = 0; it < 8; it++) {          // B: 1024 16B chunks
        int i = tid + it * 128;
        int r = i >> 3, kc = i & 7;
        cp16(&Bs[r * P + kc * 8], g_wk + (size_t)(bn + r) * 1024 + z * 64 + kc * 8);
    }
    cp_commit(); cp_wait<0>();
    __syncthreads();

    float acc[2][8][4];
#pragma unroll
    for (int i = 0; i < 2; i++)
#pragma unroll
        for (int j = 0; j < 8; j++)
#pragma unroll
            for (int k = 0; k < 4; k++) acc[i][j][k] = 0.f;

#pragma unroll
    for (int kk = 0; kk < 64; kk += 16) {
        int cc = kk + (lane & 3) * 2;
        uint32_t af[2][4];
#pragma unroll
        for (int mf = 0; mf < 2; mf++) {
            int r = wm + mf * 16 + (lane >> 2);
            af[mf][0] = *(const uint32_t*)&As[r * P + cc];
            af[mf][1] = *(const uint32_t*)&As[(r + 8) * P + cc];
            af[mf][2] = *(const uint32_t*)&As[r * P + cc + 8];
            af[mf][3] = *(const uint32_t*)&As[(r + 8) * P + cc + 8];
        }
        uint32_t bfr[8][2];
#pragma unroll
        for (int nf = 0; nf < 8; nf++) {
            int nn = wn + nf * 8 + (lane >> 2);
            bfr[nf][0] = *(const uint32_t*)&Bs[nn * P + cc];
            bfr[nf][1] = *(const uint32_t*)&Bs[nn * P + cc + 8];
        }
#pragma unroll
        for (int mf = 0; mf < 2; mf++)
#pragma unroll
            for (int nf = 0; nf < 8; nf++)
                mma16816(acc[mf][nf], af[mf], bfr[nf]);
    }
    __syncthreads();   // done with As/Bs; reuse as staging

#pragma unroll
    for (int mf = 0; mf < 2; mf++) {
#pragma unroll
        for (int nf = 0; nf < 8; nf++) {
            int r = wm + mf * 16 + (lane >> 2);
            int c = wn + nf * 8 + (lane & 3) * 2;
            *(uint32_t*)&Cs[r * CP + c]       = packbf2(acc[mf][nf][0], acc[mf][nf][1]);
            *(uint32_t*)&Cs[(r + 8) * CP + c] = packbf2(acc[mf][nf][2], acc[mf][nf][3]);
        }
    }
    __syncthreads();

    // coalesced copy-out: 64 rows x 256B into interleaved u[n][h][d]
    bf16* C = g_u + (size_t)bm * 16384 + (size_t)z * 1024 + bn;
#pragma unroll
    for (int it = 0; it < 8; it++) {
        int i = tid + it * 128;
        int r = i >> 4, cc = (i & 15) * 8;
        *(float4*)(C + (size_t)r * 16384 + cc) = *(const float4*)&Cs[r * CP + cc];
    }
}

// ---------------------------------------------------------------------------
// attn_fused (r13, measured): 288 threads (9 warps).
// ---------------------------------------------------------------------------
__global__ void __launch_bounds__(288) attn_fused_kernel(
    const float* __restrict__ feat, const float* __restrict__ ctx,
    const float* __restrict__ gc, const float* __restrict__ bc)
{
    __shared__ __align__(16) bf16 cn_s[9 * 1024];   // 18 KB
    __shared__ float att[144];
    int n = blockIdx.x, tid = threadIdx.x, lane = tid & 31, wid = tid >> 5;

    // ---- Phase A: warp-parallel LN_c (warp l handles row l) ----
    {
        int l = wid;
        const float* src = (l == 0) ? feat + (size_t)n * 1024
                                    : ctx + ((size_t)n * 8 + (l - 1)) * 1024;
        float4 x[8];
        float s = 0.f;
#pragma unroll
        for (int j = 0; j < 8; j++) {
            x[j] = ((const float4*)src)[lane + j * 32];
            s += (x[j].x + x[j].y) + (x[j].z + x[j].w);
        }
#pragma unroll
        for (int o = 16; o > 0; o >>= 1) s += __shfl_xor_sync(0xffffffffu, s, o);
        float mean = s * (1.0f / 1024.0f);
        float sq = 0.f;
#pragma unroll
        for (int j = 0; j < 8; j++) {
            x[j].x -= mean; x[j].y -= mean; x[j].z -= mean; x[j].w -= mean;
            sq += x[j].x * x[j].x + x[j].y * x[j].y
                + x[j].z * x[j].z + x[j].w * x[j].w;
        }
#pragma unroll
        for (int o = 16; o > 0; o >>= 1) sq += __shfl_xor_sync(0xffffffffu, sq, o);
        float rs = rsqrtf(sq * (1.0f / 1024.0f) + 1e-5f);
#pragma unroll
        for (int j = 0; j < 8; j++) {
            int idx = lane + j * 32;
            float4 g = ((const float4*)gc)[idx];
            float4 b = ((const float4*)bc)[idx];
            *(uint2*)(cn_s + l * 1024 + idx * 4) = make_uint2(
                packbf2(x[j].x * rs * g.x + b.x, x[j].y * rs * g.y + b.y),
                packbf2(x[j].z * rs * g.z + b.z, x[j].w * rs * g.w + b.w));
        }
    }
    __syncthreads();

    // ---- Phase B: scores (warps 0..7, heads {w, w+8}, u in registers) ----
    if (wid < 8) {
        uint4 u0[4], u1[4];
        const uint4* ga = (const uint4*)(g_u + (size_t)n * 16384 + (size_t)wid * 1024);
        const uint4* gb = (const uint4*)(g_u + (size_t)n * 16384 + (size_t)(wid + 8) * 1024);
#pragma unroll
        for (int j = 0; j < 4; j++) { u0[j] = ga[lane + j * 32]; u1[j] = gb[lane + j * 32]; }

#pragma unroll
        for (int l = 0; l < 9; l++) {
            const uint4* cc = (const uint4*)(cn_s + l * 1024);
            float s0 = 0.f, s1 = 0.f;
#pragma unroll
            for (int j = 0; j < 4; j++) {
                uint4 cb = cc[lane + j * 32];
                const uint32_t* cw = &cb.x;
                const uint32_t* aw = &u0[j].x;
                const uint32_t* bw = &u1[j].x;
#pragma unroll
                for (int q = 0; q < 4; q++) {
                    float2 cv = __bfloat1622float2(*(__nv_bfloat162*)&cw[q]);
                    float2 av = __bfloat1622float2(*(__nv_bfloat162*)&aw[q]);
                    float2 bv = __bfloat1622float2(*(__nv_bfloat162*)&bw[q]);
                    s0 = fmaf(av.x, cv.x, fmaf(av.y, cv.y, s0));
                    s1 = fmaf(bv.x, cv.x, fmaf(bv.y, cv.y, s1));
                }
            }
#pragma unroll
            for (int o = 16; o > 0; o >>= 1) {
                s0 += __shfl_xor_sync(0xffffffffu, s0, o);
                s1 += __shfl_xor_sync(0xffffffffu, s1, o);
            }
            if (lane == 0) {
                att[wid * 9 + l]       = s0;
                att[(wid + 8) * 9 + l] = s1;
            }
        }
    }
    __syncthreads();

    // ---- softmax over l (scale 0.125) ----
    if (tid < 16) {
        float m = -1e30f;
#pragma unroll
        for (int l = 0; l < 9; l++) m = fmaxf(m, att[tid * 9 + l]);
        float e[9], sum = 0.f;
#pragma unroll
        for (int l = 0; l < 9; l++) {
            e[l] = __expf((att[tid * 9 + l] - m) * 0.125f);
            sum += e[l];
        }
        float inv = 1.0f / sum;
#pragma unroll
        for (int l = 0; l < 9; l++) att[tid * 9 + l] = e[l] * inv;
    }
    __syncthreads();

    // ---- w-phase: one pass, 4 bf16 per thread (uint2 LDS + uint2 STG) ----
    if (tid < 256) {
        bf16* ug = g_u + (size_t)n * 16384;
        int dp4 = tid;
        float2 c[9][2];
#pragma unroll
        for (int l = 0; l < 9; l++) {
            uint2 v = ((const uint2*)cn_s)[l * 256 + dp4];
            c[l][0] = __bfloat1622float2(*(__nv_bfloat162*)&v.x);
            c[l][1] = __bfloat1622float2(*(__nv_bfloat162*)&v.y);
        }
#pragma unroll
        for (int h = 0; h < 16; h++) {
            float s0 = 0.f, s1 = 0.f, s2 = 0.f, s3 = 0.f;
#pragma unroll
            for (int l = 0; l < 9; l++) {
                float a = att[h * 9 + l];
                s0 = fmaf(a, c[l][0].x, s0);
                s1 = fmaf(a, c[l][0].y, s1);
                s2 = fmaf(a, c[l][1].x, s2);
                s3 = fmaf(a, c[l][1].y, s3);
            }
            *(uint2*)(ug + h * 1024 + dp4 * 4)
                = make_uint2(packbf2(s0, s1), packbf2(s2, s3));
        }
    }
}

// ---------------------------------------------------------------------------
extern "C" void kernel_launch(void* const* d_in, const int* in_sizes, int n_in,
                              void* d_out, int out_size)
{
    const float* feat    = (const float*)d_in[0];
    const float* context = (const float*)d_in[1];
    const float* ln_q_g  = (const float*)d_in[2];
    const float* ln_q_b  = (const float*)d_in[3];
    const float* ln_c_g  = (const float*)d_in[4];
    const float* ln_c_b  = (const float*)d_in[5];
    const float* Wq      = (const float*)d_in[6];
    const float* Wk      = (const float*)d_in[7];
    const float* Wv      = (const float*)d_in[8];
    const float* Wout    = (const float*)d_in[9];
    const float* bout    = (const float*)d_in[10];
    float* out = (float*)d_out;
    (void)in_sizes; (void)n_in; (void)out_size;

    bf16 *p_qn, *p_q, *p_u, *p_o, *p_wq, *p_wv, *p_wo;
    cudaGetSymbolAddress((void**)&p_qn, g_qn);
    cudaGetSymbolAddress((void**)&p_q,  g_q);
    cudaGetSymbolAddress((void**)&p_u,  g_u);
    cudaGetSymbolAddress((void**)&p_o,  g_o);
    cudaGetSymbolAddress((void**)&p_wq, g_wq);
    cudaGetSymbolAddress((void**)&p_wv, g_wv);
    cudaGetSymbolAddress((void**)&p_wo, g_wo);

    const int SMEM_BN128 = (2 * 128 * 72 + 2 * 64 * 136) * 2;   // 71680 B
    const int SMEM_BN64  = (2 * 128 * 72 + 2 * 64 * 72) * 2;    // 55296 B
    cudaFuncSetAttribute(gemm_bf16<128, false, false>,
                         cudaFuncAttributeMaxDynamicSharedMemorySize, SMEM_BN128);
    cudaFuncSetAttribute(gemm_bf16<128, true, true>,
                         cudaFuncAttributeMaxDynamicSharedMemorySize, SMEM_BN128);
    cudaFuncSetAttribute(gemm_bf16<64, false, false>,
                         cudaFuncAttributeMaxDynamicSharedMemorySize, SMEM_BN64);

    // 0) weights fp32 -> bf16
    cvt_kernel<<<1024, 256>>>(Wq, Wk, Wv, Wout);

    // 1) qn = LN_q(feat)
    ln_q_kernel<<<NROWS, 256>>>(feat, ln_q_g, ln_q_b);

    // 2) q = qn @ Wq
    gemm_bf16<128, false, false><<<dim3(8, 256, 1), 256, SMEM_BN128>>>(
        p_qn, 0, 1024, p_wq, 0, 1024, p_q, 0, 1024, 1024, nullptr, nullptr);

    // 3) u[n][z] = q_z @ Wk_z^T  (K=64, one-shot [64n x 128d] blocks)
    gemm_qk_kernel<<<dim3(8, 512, 16), 128>>>();

    // 4) fused warp-parallel LN_c + scores + softmax + w (in place over u)
    attn_fused_kernel<<<NROWS, 288>>>(feat, context, ln_c_g, ln_c_b);

    // 5) o_z = w_z @ Wv_z
    gemm_bf16<64, false, false><<<dim3(1, 256, 16), 256, SMEM_BN64>>>(
        p_u, 1024, 16384, p_wv, 64, 1024, p_o, 64, 1024, 1024, nullptr, nullptr);

    // 6) out = o @ Wout + bout + feat  (fp32)
    gemm_bf16<128, true, true><<<dim3(8, 256, 1), 256, SMEM_BN128>>>(
        p_o, 0, 1024, p_wo, 0, 1024, out, 0, 1024, 1024, bout, feat);
}

// round 17
// speedup vs baseline: 1.0116x; 1.0030x over previous
#include <cuda_runtime.h>
#include <cuda_bf16.h>
#include <cstdint>
#include <cstddef>

// ---------------------------------------------------------------------------
// InputAttention on GB300 — round 16
//   Base = r15 (1845us best). Changes:
//     * u/w scratch switched to head-major planes u[z][n][d] (r3 layout,
//       proven equivalent for qk/attn): gemm_wv's A operand becomes a
//       contiguous plane (lda 16384 -> 1024), qk stores at 2KB stride.
//     * gemm6 epilogue bias/resid loads vectorized (float2).
//   All numerics identical.
// ---------------------------------------------------------------------------

#define NROWS 32768
using bf16 = __nv_bfloat16;

__device__ bf16 g_qn[(size_t)NROWS * 1024];
__device__ bf16 g_q [(size_t)NROWS * 1024];
__device__ bf16 g_u [(size_t)16 * NROWS * 1024];   // head-major planes; w in place
__device__ bf16 g_o [(size_t)NROWS * 1024];
__device__ bf16 g_wq[1024 * 1024];
__device__ bf16 g_wk[1024 * 1024];
__device__ bf16 g_wv[1024 * 1024];
__device__ bf16 g_wo[1024 * 1024];

// ---------------- PTX helpers ----------------
__device__ __forceinline__ uint32_t smem_u32(const void* p) {
    return (uint32_t)__cvta_generic_to_shared(p);
}
__device__ __forceinline__ void cp16(void* s, const void* g) {
    asm volatile("cp.async.cg.shared.global [%0], [%1], 16;"
                 :: "r"(smem_u32(s)), "l"(g));
}
__device__ __forceinline__ void cp_commit() { asm volatile("cp.async.commit_group;"); }
template<int N> __device__ __forceinline__ void cp_wait() {
    asm volatile("cp.async.wait_group %0;" :: "n"(N));
}
__device__ __forceinline__ void ldsm4(uint32_t* r, const void* p) {
    asm volatile("ldmatrix.sync.aligned.m8n8.x4.shared.b16 {%0,%1,%2,%3},[%4];"
        : "=r"(r[0]), "=r"(r[1]), "=r"(r[2]), "=r"(r[3]) : "r"(smem_u32(p)));
}
__device__ __forceinline__ void ldsm4t(uint32_t* r, const void* p) {
    asm volatile("ldmatrix.sync.aligned.m8n8.x4.trans.shared.b16 {%0,%1,%2,%3},[%4];"
        : "=r"(r[0]), "=r"(r[1]), "=r"(r[2]), "=r"(r[3]) : "r"(smem_u32(p)));
}
__device__ __forceinline__ void mma16816(float* c, const uint32_t* a, const uint32_t* b) {
    asm volatile(
        "mma.sync.aligned.m16n8k16.row.col.f32.bf16.bf16.f32 "
        "{%0,%1,%2,%3},{%4,%5,%6,%7},{%8,%9},{%0,%1,%2,%3};"
        : "+f"(c[0]), "+f"(c[1]), "+f"(c[2]), "+f"(c[3])
        : "r"(a[0]), "r"(a[1]), "r"(a[2]), "r"(a[3]), "r"(b[0]), "r"(b[1]));
}
__device__ __forceinline__ uint32_t packbf2(float x, float y) {
    __nv_bfloat162 h = __float22bfloat162_rn(make_float2(x, y));
    return *reinterpret_cast<uint32_t*>(&h);
}

// ---------------- weight convert (fp32 -> bf16) ----------------
__global__ void __launch_bounds__(256) cvt_kernel(
    const float* __restrict__ wq, const float* __restrict__ wk,
    const float* __restrict__ wv, const float* __restrict__ wo)
{
    int i = blockIdx.x * 256 + threadIdx.x;
    float4 a = ((const float4*)wq)[i];
    ((uint2*)g_wq)[i] = make_uint2(packbf2(a.x, a.y), packbf2(a.z, a.w));
    a = ((const float4*)wk)[i];
    ((uint2*)g_wk)[i] = make_uint2(packbf2(a.x, a.y), packbf2(a.z, a.w));
    a = ((const float4*)wv)[i];
    ((uint2*)g_wv)[i] = make_uint2(packbf2(a.x, a.y), packbf2(a.z, a.w));
    a = ((const float4*)wo)[i];
    ((uint2*)g_wo)[i] = make_uint2(packbf2(a.x, a.y), packbf2(a.z, a.w));
}

// ---------------- block reduce (for ln_q) ----------------
__device__ __forceinline__ float block_reduce_sum(float v, float* sh) {
#pragma unroll
    for (int o = 16; o > 0; o >>= 1) v += __shfl_xor_sync(0xffffffffu, v, o);
    int lane = threadIdx.x & 31, w = threadIdx.x >> 5;
    if (lane == 0) sh[w] = v;
    __syncthreads();
    if (threadIdx.x < 8) {
        float t = sh[threadIdx.x];
#pragma unroll
        for (int o = 4; o > 0; o >>= 1) t += __shfl_xor_sync(0xffu, t, o);
        if (threadIdx.x == 0) sh[0] = t;
    }
    __syncthreads();
    float r = sh[0];
    __syncthreads();
    return r;
}

// ---------------- LN_q: qn = LN(feat) (bf16), block-per-row ----------------
__global__ void __launch_bounds__(256) ln_q_kernel(
    const float* __restrict__ feat,
    const float* __restrict__ gq, const float* __restrict__ bq)
{
    __shared__ float sh[8];
    int n = blockIdx.x, tid = threadIdx.x;
    float4 x = ((const float4*)(feat + (size_t)n * 1024))[tid];
    float s = block_reduce_sum(x.x + x.y + x.z + x.w, sh);
    float mean = s * (1.0f / 1024.0f);
    float dx = x.x - mean, dy = x.y - mean, dz = x.z - mean, dw = x.w - mean;
    float sq = block_reduce_sum(dx * dx + dy * dy + dz * dz + dw * dw, sh);
    float rs = rsqrtf(sq * (1.0f / 1024.0f) + 1e-5f);
    float4 g = ((const float4*)gq)[tid];
    float4 b = ((const float4*)bq)[tid];
    *reinterpret_cast<uint2*>(g_qn + (size_t)n * 1024 + tid * 4) = make_uint2(
        packbf2(dx * rs * g.x + b.x, dy * rs * g.y + b.y),
        packbf2(dz * rs * g.z + b.z, dw * rs * g.w + b.w));
}

// ---------------------------------------------------------------------------
// Standard bf16 GEMM (r10/r13): BK=64, 2-stage cp.async, dynamic smem.
// ---------------------------------------------------------------------------
template<int BN, bool EPI, bool CF32>
__global__ void __launch_bounds__(256) gemm_bf16(
    const bf16* __restrict__ A, long aBS, int lda,
    const bf16* __restrict__ B, long bBS, int ldb,
    void* __restrict__ Cv, long cBS, int ldc,
    int K, const float* __restrict__ bias, const float* __restrict__ resid)
{
    constexpr int BM = 128, BK = 64;
    constexpr int AP = BK + 8;
    constexpr int BP = BN + 8;
    constexpr int NF = BN / 16;
    extern __shared__ __align__(16) bf16 dsm[];
    bf16* As = dsm;
    bf16* Bs = dsm + 2 * BM * AP;

    int z = blockIdx.z;
    A += (size_t)z * aBS;
    B += (size_t)z * bBS;

    int bm = blockIdx.y * BM, bn = blockIdx.x * BN;
    int tid = threadIdx.x, lane = tid & 31, wid = tid >> 5;
    int wm = (wid >> 1) * 32, wn = (wid & 1) * (BN / 2);

    float acc[2][NF][4];
#pragma unroll
    for (int i = 0; i < 2; i++)
#pragma unroll
        for (int j = 0; j < NF; j++)
#pragma unroll
            for (int k = 0; k < 4; k++) acc[i][j][k] = 0.f;

    auto loadA = [&](int buf, int k0) {
        bf16* dst = As + buf * BM * AP;
#pragma unroll
        for (int it = 0; it < 4; it++) {
            int i = tid + it * 256;
            int r = i >> 3, kc = i & 7;
            cp16(dst + r * AP + kc * 8,
                 A + (size_t)(bm + r) * lda + k0 + kc * 8);
        }
    };
    auto loadB = [&](int buf, int k0) {
        bf16* dst = Bs + buf * BK * BP;
        constexpr int CH = BK * BN / 8;
#pragma unroll
        for (int it = 0; it < CH / 256; it++) {
            int i = tid + it * 256;
            int r = i / (BN / 8), nc = i % (BN / 8);
            cp16(dst + r * BP + nc * 8,
                 B + (size_t)(k0 + r) * ldb + bn + nc * 8);
        }
    };
    auto compute = [&](int buf) {
        const bf16* a_s = As + buf * BM * AP;
        const bf16* b_s = Bs + buf * BK * BP;
#pragma unroll
        for (int kk = 0; kk < BK; kk += 16) {
            uint32_t af[2][4];
#pragma unroll
            for (int mf = 0; mf < 2; mf++) {
                int r = wm + mf * 16 + ((lane >> 3) & 1) * 8 + (lane & 7);
                int c = kk + (lane >> 4) * 8;
                ldsm4(af[mf], a_s + r * AP + c);
            }
            uint32_t bfr[NF][2];
#pragma unroll
            for (int n2 = 0; n2 < NF / 2; n2++) {
                int kr = kk + ((lane >> 3) & 1) * 8 + (lane & 7);
                int nc = wn + n2 * 16 + (lane >> 4) * 8;
                uint32_t t[4];
                ldsm4t(t, b_s + kr * BP + nc);
                bfr[2 * n2][0] = t[0];     bfr[2 * n2][1] = t[1];
                bfr[2 * n2 + 1][0] = t[2]; bfr[2 * n2 + 1][1] = t[3];
            }
#pragma unroll
            for (int mf = 0; mf < 2; mf++)
#pragma unroll
                for (int nf = 0; nf < NF; nf++)
                    mma16816(acc[mf][nf], af[mf], bfr[nf]);
        }
    };

    loadA(0, 0); loadB(0, 0); cp_commit();
    int nIter = K / BK;
    for (int it = 0; it < nIter; it++) {
        if (it + 1 < nIter) {
            loadA((it + 1) & 1, (it + 1) * BK);
            loadB((it + 1) & 1, (it + 1) * BK);
            cp_commit();
            cp_wait<1>();
        } else {
            cp_wait<0>();
        }
        __syncthreads();
        compute(it & 1);
        __syncthreads();
    }

#pragma unroll
    for (int mf = 0; mf < 2; mf++) {
#pragma unroll
        for (int nf = 0; nf < NF; nf++) {
            int r = bm + wm + mf * 16 + (lane >> 2);
            int c = bn + wn + nf * 8 + (lane & 3) * 2;
            float v0 = acc[mf][nf][0], v1 = acc[mf][nf][1];
            float v2 = acc[mf][nf][2], v3 = acc[mf][nf][3];
            if constexpr (CF32) {
                float* C = (float*)Cv + (size_t)z * cBS;
                if constexpr (EPI) {
                    float2 bb  = *(const float2*)&bias[c];
                    float2 r0v = *(const float2*)&resid[(size_t)r * ldc + c];
                    float2 r1v = *(const float2*)&resid[(size_t)(r + 8) * ldc + c];
                    v0 += bb.x + r0v.x; v1 += bb.y + r0v.y;
                    v2 += bb.x + r1v.x; v3 += bb.y + r1v.y;
                }
                *(float2*)&C[(size_t)r * ldc + c]       = make_float2(v0, v1);
                *(float2*)&C[(size_t)(r + 8) * ldc + c] = make_float2(v2, v3);
            } else {
                bf16* C = (bf16*)Cv + (size_t)z * cBS;
                *(uint32_t*)&C[(size_t)r * ldc + c]       = packbf2(v0, v1);
                *(uint32_t*)&C[(size_t)(r + 8) * ldc + c] = packbf2(v2, v3);
            }
        }
    }
}

// ---------------------------------------------------------------------------
// gemm_qk (r15 geometry): one-shot [64n x 128d] blocks, 128 threads,
// K=64 resident, smem-staged coalesced stores into head-major u[z][n][d].
// ---------------------------------------------------------------------------
__global__ void __launch_bounds__(128) gemm_qk_kernel()
{
    constexpr int P = 72;
    constexpr int CP = 136;
    __shared__ __align__(16) char smem_raw[(64 * P + 128 * P) * 2];
    bf16* As = (bf16*)smem_raw;
    bf16* Bs = (bf16*)(smem_raw + 64 * P * 2);
    bf16* Cs = (bf16*)smem_raw;

    int z = blockIdx.z;
    int bm = blockIdx.y * 64, bn = blockIdx.x * 128;
    int tid = threadIdx.x, lane = tid & 31, wid = tid >> 5;
    int wm = (wid >> 1) * 32, wn = (wid & 1) * 64;

#pragma unroll
    for (int it = 0; it < 4; it++) {
        int i = tid + it * 128;
        int r = i >> 3, kc = i & 7;
        cp16(&As[r * P + kc * 8], g_q + (size_t)(bm + r) * 1024 + z * 64 + kc * 8);
    }
#pragma unroll
    for (int it = 0; it < 8; it++) {
        int i = tid + it * 128;
        int r = i >> 3, kc = i & 7;
        cp16(&Bs[r * P + kc * 8], g_wk + (size_t)(bn + r) * 1024 + z * 64 + kc * 8);
    }
    cp_commit(); cp_wait<0>();
    __syncthreads();

    float acc[2][8][4];
#pragma unroll
    for (int i = 0; i < 2; i++)
#pragma unroll
        for (int j = 0; j < 8; j++)
#pragma unroll
            for (int k = 0; k < 4; k++) acc[i][j][k] = 0.f;

#pragma unroll
    for (int kk = 0; kk < 64; kk += 16) {
        int cc = kk + (lane & 3) * 2;
        uint32_t af[2][4];
#pragma unroll
        for (int mf = 0; mf < 2; mf++) {
            int r = wm + mf * 16 + (lane >> 2);
            af[mf][0] = *(const uint32_t*)&As[r * P + cc];
            af[mf][1] = *(const uint32_t*)&As[(r + 8) * P + cc];
            af[mf][2] = *(const uint32_t*)&As[r * P + cc + 8];
            af[mf][3] = *(const uint32_t*)&As[(r + 8) * P + cc + 8];
        }
        uint32_t bfr[8][2];
#pragma unroll
        for (int nf = 0; nf < 8; nf++) {
            int nn = wn + nf * 8 + (lane >> 2);
            bfr[nf][0] = *(const uint32_t*)&Bs[nn * P + cc];
            bfr[nf][1] = *(const uint32_t*)&Bs[nn * P + cc + 8];
        }
#pragma unroll
        for (int mf = 0; mf < 2; mf++)
#pragma unroll
            for (int nf = 0; nf < 8; nf++)
                mma16816(acc[mf][nf], af[mf], bfr[nf]);
    }
    __syncthreads();

#pragma unroll
    for (int mf = 0; mf < 2; mf++) {
#pragma unroll
        for (int nf = 0; nf < 8; nf++) {
            int r = wm + mf * 16 + (lane >> 2);
            int c = wn + nf * 8 + (lane & 3) * 2;
            *(uint32_t*)&Cs[r * CP + c]       = packbf2(acc[mf][nf][0], acc[mf][nf][1]);
            *(uint32_t*)&Cs[(r + 8) * CP + c] = packbf2(acc[mf][nf][2], acc[mf][nf][3]);
        }
    }
    __syncthreads();

    // coalesced copy-out: 64 rows x 256B into head-major u[z][n][d]
    bf16* C = g_u + ((size_t)z * NROWS + bm) * 1024 + bn;
#pragma unroll
    for (int it = 0; it < 8; it++) {
        int i = tid + it * 128;
        int r = i >> 4, cc = (i & 15) * 8;
        *(float4*)(C + (size_t)r * 1024 + cc) = *(const float4*)&Cs[r * CP + cc];
    }
}

// ---------------------------------------------------------------------------
// attn_fused (r13/r15 core, head-major u): 288 threads (9 warps).
// ---------------------------------------------------------------------------
__global__ void __launch_bounds__(288) attn_fused_kernel(
    const float* __restrict__ feat, const float* __restrict__ ctx,
    const float* __restrict__ gc, const float* __restrict__ bc)
{
    __shared__ __align__(16) bf16 cn_s[9 * 1024];   // 18 KB
    __shared__ float att[144];
    int n = blockIdx.x, tid = threadIdx.x, lane = tid & 31, wid = tid >> 5;

    // ---- Phase A: warp-parallel LN_c (warp l handles row l) ----
    {
        int l = wid;
        const float* src = (l == 0) ? feat + (size_t)n * 1024
                                    : ctx + ((size_t)n * 8 + (l - 1)) * 1024;
        float4 x[8];
        float s = 0.f;
#pragma unroll
        for (int j = 0; j < 8; j++) {
            x[j] = ((const float4*)src)[lane + j * 32];
            s += (x[j].x + x[j].y) + (x[j].z + x[j].w);
        }
#pragma unroll
        for (int o = 16; o > 0; o >>= 1) s += __shfl_xor_sync(0xffffffffu, s, o);
        float mean = s * (1.0f / 1024.0f);
        float sq = 0.f;
#pragma unroll
        for (int j = 0; j < 8; j++) {
            x[j].x -= mean; x[j].y -= mean; x[j].z -= mean; x[j].w -= mean;
            sq += x[j].x * x[j].x + x[j].y * x[j].y
                + x[j].z * x[j].z + x[j].w * x[j].w;
        }
#pragma unroll
        for (int o = 16; o > 0; o >>= 1) sq += __shfl_xor_sync(0xffffffffu, sq, o);
        float rs = rsqrtf(sq * (1.0f / 1024.0f) + 1e-5f);
#pragma unroll
        for (int j = 0; j < 8; j++) {
            int idx = lane + j * 32;
            float4 g = ((const float4*)gc)[idx];
            float4 b = ((const float4*)bc)[idx];
            *(uint2*)(cn_s + l * 1024 + idx * 4) = make_uint2(
                packbf2(x[j].x * rs * g.x + b.x, x[j].y * rs * g.y + b.y),
                packbf2(x[j].z * rs * g.z + b.z, x[j].w * rs * g.w + b.w));
        }
    }
    __syncthreads();

    // ---- Phase B: scores (warps 0..7, heads {w, w+8}, u in registers) ----
    if (wid < 8) {
        uint4 u0[4], u1[4];
        const uint4* ga = (const uint4*)(g_u + ((size_t)wid * NROWS + n) * 1024);
        const uint4* gb = (const uint4*)(g_u + ((size_t)(wid + 8) * NROWS + n) * 1024);
#pragma unroll
        for (int j = 0; j < 4; j++) { u0[j] = ga[lane + j * 32]; u1[j] = gb[lane + j * 32]; }

#pragma unroll
        for (int l = 0; l < 9; l++) {
            const uint4* cc = (const uint4*)(cn_s + l * 1024);
            float s0 = 0.f, s1 = 0.f;
#pragma unroll
            for (int j = 0; j < 4; j++) {
                uint4 cb = cc[lane + j * 32];
                const uint32_t* cw = &cb.x;
                const uint32_t* aw = &u0[j].x;
                const uint32_t* bw = &u1[j].x;
#pragma unroll
                for (int q = 0; q < 4; q++) {
                    float2 cv = __bfloat1622float2(*(__nv_bfloat162*)&cw[q]);
                    float2 av = __bfloat1622float2(*(__nv_bfloat162*)&aw[q]);
                    float2 bv = __bfloat1622float2(*(__nv_bfloat162*)&bw[q]);
                    s0 = fmaf(av.x, cv.x, fmaf(av.y, cv.y, s0));
                    s1 = fmaf(bv.x, cv.x, fmaf(bv.y, cv.y, s1));
                }
            }
#pragma unroll
            for (int o = 16; o > 0; o >>= 1) {
                s0 += __shfl_xor_sync(0xffffffffu, s0, o);
                s1 += __shfl_xor_sync(0xffffffffu, s1, o);
            }
            if (lane == 0) {
                att[wid * 9 + l]       = s0;
                att[(wid + 8) * 9 + l] = s1;
            }
        }
    }
    __syncthreads();

    // ---- softmax over l (scale 0.125) ----
    if (tid < 16) {
        float m = -1e30f;
#pragma unroll
        for (int l = 0; l < 9; l++) m = fmaxf(m, att[tid * 9 + l]);
        float e[9], sum = 0.f;
#pragma unroll
        for (int l = 0; l < 9; l++) {
            e[l] = __expf((att[tid * 9 + l] - m) * 0.125f);
            sum += e[l];
        }
        float inv = 1.0f / sum;
#pragma unroll
        for (int l = 0; l < 9; l++) att[tid * 9 + l] = e[l] * inv;
    }
    __syncthreads();

    // ---- w-phase: one pass, 4 bf16 per thread (uint2 LDS + uint2 STG) ----
    if (tid < 256) {
        int dp4 = tid;
        float2 c[9][2];
#pragma unroll
        for (int l = 0; l < 9; l++) {
            uint2 v = ((const uint2*)cn_s)[l * 256 + dp4];
            c[l][0] = __bfloat1622float2(*(__nv_bfloat162*)&v.x);
            c[l][1] = __bfloat1622float2(*(__nv_bfloat162*)&v.y);
        }
#pragma unroll
        for (int h = 0; h < 16; h++) {
            float s0 = 0.f, s1 = 0.f, s2 = 0.f, s3 = 0.f;
#pragma unroll
            for (int l = 0; l < 9; l++) {
                float a = att[h * 9 + l];
                s0 = fmaf(a, c[l][0].x, s0);
                s1 = fmaf(a, c[l][0].y, s1);
                s2 = fmaf(a, c[l][1].x, s2);
                s3 = fmaf(a, c[l][1].y, s3);
            }
            *(uint2*)(g_u + ((size_t)h * NROWS + n) * 1024 + dp4 * 4)
                = make_uint2(packbf2(s0, s1), packbf2(s2, s3));
        }
    }
}

// ---------------------------------------------------------------------------
extern "C" void kernel_launch(void* const* d_in, const int* in_sizes, int n_in,
                              void* d_out, int out_size)
{
    const float* feat    = (const float*)d_in[0];
    const float* context = (const float*)d_in[1];
    const float* ln_q_g  = (const float*)d_in[2];
    const float* ln_q_b  = (const float*)d_in[3];
    const float* ln_c_g  = (const float*)d_in[4];
    const float* ln_c_b  = (const float*)d_in[5];
    const float* Wq      = (const float*)d_in[6];
    const float* Wk      = (const float*)d_in[7];
    const float* Wv      = (const float*)d_in[8];
    const float* Wout    = (const float*)d_in[9];
    const float* bout    = (const float*)d_in[10];
    float* out = (float*)d_out;
    (void)in_sizes; (void)n_in; (void)out_size;

    bf16 *p_qn, *p_q, *p_u, *p_o, *p_wq, *p_wv, *p_wo;
    cudaGetSymbolAddress((void**)&p_qn, g_qn);
    cudaGetSymbolAddress((void**)&p_q,  g_q);
    cudaGetSymbolAddress((void**)&p_u,  g_u);
    cudaGetSymbolAddress((void**)&p_o,  g_o);
    cudaGetSymbolAddress((void**)&p_wq, g_wq);
    cudaGetSymbolAddress((void**)&p_wv, g_wv);
    cudaGetSymbolAddress((void**)&p_wo, g_wo);

    const int SMEM_BN128 = (2 * 128 * 72 + 2 * 64 * 136) * 2;   // 71680 B
    const int SMEM_BN64  = (2 * 128 * 72 + 2 * 64 * 72) * 2;    // 55296 B
    cudaFuncSetAttribute(gemm_bf16<128, false, false>,
                         cudaFuncAttributeMaxDynamicSharedMemorySize, SMEM_BN128);
    cudaFuncSetAttribute(gemm_bf16<128, true, true>,
                         cudaFuncAttributeMaxDynamicSharedMemorySize, SMEM_BN128);
    cudaFuncSetAttribute(gemm_bf16<64, false, false>,
                         cudaFuncAttributeMaxDynamicSharedMemorySize, SMEM_BN64);

    // 0) weights fp32 -> bf16
    cvt_kernel<<<1024, 256>>>(Wq, Wk, Wv, Wout);

    // 1) qn = LN_q(feat)
    ln_q_kernel<<<NROWS, 256>>>(feat, ln_q_g, ln_q_b);

    // 2) q = qn @ Wq
    gemm_bf16<128, false, false><<<dim3(8, 256, 1), 256, SMEM_BN128>>>(
        p_qn, 0, 1024, p_wq, 0, 1024, p_q, 0, 1024, 1024, nullptr, nullptr);

    // 3) u[z][n][d] = q_z @ Wk_z^T  (K=64, one-shot [64n x 128d] blocks)
    gemm_qk_kernel<<<dim3(8, 512, 16), 128>>>();

    // 4) fused warp-parallel LN_c + scores + softmax + w (in place over u planes)
    attn_fused_kernel<<<NROWS, 288>>>(feat, context, ln_c_g, ln_c_b);

    // 5) o_z = w_z @ Wv_z   (A = contiguous head plane, lda=1024)
    gemm_bf16<64, false, false><<<dim3(1, 256, 16), 256, SMEM_BN64>>>(
        p_u, (long)NROWS * 1024, 1024, p_wv, 64, 1024, p_o, 64, 1024,
        1024, nullptr, nullptr);

    // 6) out = o @ Wout + bout + feat  (fp32, vectorized epilogue)
    gemm_bf16<128, true, true><<<dim3(8, 256, 1), 256, SMEM_BN128>>>(
        p_o, 0, 1024, p_wo, 0, 1024, out, 0, 1024, 1024, bout, feat);
}